// round 11
// baseline (speedup 1.0000x reference)
#include <cuda_runtime.h>
#include <cuda_fp16.h>
#include <cstdint>

// ---------------------------------------------------------------------------
// Round 11: hybrid tensor + FMA with DURATION-MATCHED CTAs.
// R10 diagnosis: FFMA CTA (128 rows) ran ~70us vs ~17us tensor CTA -> slot
// pinning + tail. R11: FFMA CTAs are 32 rows (~16us), split 452:240(x32rows)
// = 88.3%:11.7%, Bresenham-interleaved. Tensor path verbatim R6.
// ---------------------------------------------------------------------------

struct Params {
    const float* x;
    const float* w1[5]; const float* b1[5];
    const float* w2[5]; const float* b2[5];
    const float* w3[5]; const float* b3[5];
    float* out;
    int nt;     // tensor tiles (128 rows each) per node
    int nc;     // ffma CTAs (32 rows each) per node
};

__constant__ int c_gi[21]  = {0,1,1,1,2,2,3,3,3,3,3,3,3,3,3,3,4,4,4,4,4};
__constant__ int c_ki[21]  = {0,0,1,2,0,1,0,1,2,3,4,5,6,7,8,9,0,1,2,3,4};
__constant__ int c_n[21]   = {6,5,5,5,4,4,3,3,3,3,3,3,3,3,3,3,2,2,2,2,2};
__constant__ int c_out[21] = {0,5,9,13,1,17,2,3,6,7,10,11,14,15,18,19,4,8,12,16,20};
__constant__ int c_nb[21][6] = {
    {0,1,5,9,13,17},
    {0,5,6,1,9,0},  {0,9,10,5,13,0}, {0,13,14,9,17,0},
    {0,1,2,5,0,0},  {0,17,18,13,0,0},
    {1,2,3,0,0,0},  {2,3,4,0,0,0},
    {5,6,7,0,0,0},  {6,7,8,0,0,0},
    {9,10,11,0,0,0},{10,11,12,0,0,0},
    {13,14,15,0,0,0},{14,15,16,0,0,0},
    {17,18,19,0,0,0},{18,19,20,0,0,0},
    {3,4,0,0,0,0},  {7,8,0,0,0,0}, {11,12,0,0,0,0},
    {15,16,0,0,0,0},{19,20,0,0,0,0}
};
__constant__ int c_w1i_off[21] = {
    0,49152,90112,131072,172032,204800,
    237568,262144,286720,311296,335872,360448,385024,409600,434176,458752,
    483328,499712,516096,532480,548864
};

__device__ __align__(16) __half g_w1i[565248];
__device__ __align__(16) __half g_w2i[344064];
__device__ __align__(16) __half g_w3i[172032];

// Tensor-path SMEM map (bytes)
#define SM_HA 0                      // 64 tiles * 512 = 32768
#define SM_XA 32768                  // 32 tiles * 528 = 16896
#define SM_WB 49664                  // 16KB W chunk
// FFMA-path SMEM: Xs[32][68] @0 (8704) | Hs[32][132] @8704 (16896)
//                 W double buf @25600 (2 x 16384)
#define SM_FX 0
#define SM_FH 8704
#define SM_FW 25600
#define SMEM_TOTAL 100352

__device__ __forceinline__ uint32_t pkh2(float lo, float hi) {
    uint32_t r;
    asm("cvt.rn.f16x2.f32 %0, %1, %2;" : "=r"(r) : "f"(hi), "f"(lo));
    return r;
}
__device__ __forceinline__ void mma16(float c[4],
                                      uint32_t a0, uint32_t a1, uint32_t a2, uint32_t a3,
                                      uint32_t b0, uint32_t b1) {
    asm volatile(
        "mma.sync.aligned.m16n8k16.row.col.f32.f16.f16.f32 "
        "{%0,%1,%2,%3},{%4,%5,%6,%7},{%8,%9},{%0,%1,%2,%3};"
        : "+f"(c[0]), "+f"(c[1]), "+f"(c[2]), "+f"(c[3])
        : "r"(a0), "r"(a1), "r"(a2), "r"(a3), "r"(b0), "r"(b1));
}
__device__ __forceinline__ void domma(float c[4], uint2 Pg, uint2 Pg8, uint2 Pb) {
    mma16(c, Pg.x, Pg8.x, Pg.y, Pg8.y, Pb.x, Pb.y);
}

typedef unsigned long long u64;
__device__ __forceinline__ u64 dup2(float x) {
    u64 r; asm("mov.b64 %0, {%1, %1};" : "=l"(r) : "f"(x)); return r;
}
__device__ __forceinline__ void upk(u64 v, float& lo, float& hi) {
    asm("mov.b64 {%0, %1}, %2;" : "=f"(lo), "=f"(hi) : "l"(v));
}
#define FFMA2(d, a, b) \
    asm volatile("fma.rn.f32x2 %0, %1, %2, %0;" : "+l"(d) : "l"(a), "l"(b))

#define CP16(dst, src) \
    asm volatile("cp.async.ca.shared.global [%0], [%1], 16;" :: "r"(dst), "l"(src))
#define CP_WAIT() \
    asm volatile("cp.async.commit_group;\ncp.async.wait_group 0;" ::: "memory")
#define CP_COMMIT() asm volatile("cp.async.commit_group;" ::: "memory")
#define CP_WAITG1() asm volatile("cp.async.wait_group 1;" ::: "memory")
#define CP_WAIT0()  asm volatile("cp.async.wait_group 0;" ::: "memory")

__device__ __forceinline__ uint32_t smem_u32(const void* p) {
    uint32_t a;
    asm("{ .reg .u64 t; cvta.to.shared.u64 t, %1; cvt.u32.u64 %0, t; }"
        : "=r"(a) : "l"(p));
    return a;
}

// ------------------------------ prep kernel --------------------------------
__device__ __forceinline__ int imgh(int n, int k, int K16, int NK16c) {
    int jw = (k & 15) >> 1, lo = k & 1;
    int rn = n & 7, NB = n >> 3, s = (rn >> 2) & 1;
    return (NB * NK16c + K16) * 128 + rn * 16 +
           ((((jw >> 1) & 1) ^ s) << 3) + ((jw & 1) << 2) + ((jw >> 2) << 1) + lo;
}

__global__ void prep_kernel(Params p) {
    const int node = blockIdx.y;
    const int gi = c_gi[node], ki = c_ki[node], nnb = c_n[node];
    const int i = blockIdx.x * 256 + threadIdx.x;
    if (blockIdx.z == 0) {
        const int K1 = nnb * 64;
        if (i >= 128 * K1) return;
        const int k = i >> 7, n = i & 127;
        float v = p.w1[gi][((size_t)ki * K1 + k) * 128 + n];
        g_w1i[c_w1i_off[node] + (k >> 6) * 8192 + imgh(n, k, (k >> 4) & 3, 4)] =
            __float2half_rn(v);
    } else if (blockIdx.z == 1) {
        if (i >= 16384) return;
        const int k = i >> 7, n = i & 127;
        float v = p.w2[gi][(size_t)ki * 16384 + (size_t)k * 128 + n];
        g_w2i[node * 16384 + (k >> 6) * 8192 + imgh(n, k, (k >> 4) & 3, 4)] =
            __float2half_rn(v);
    } else {
        if (i >= 8192) return;
        const int k = i >> 6, n = i & 63;
        float v = p.w3[gi][(size_t)ki * 8192 + (size_t)k * 64 + n];
        g_w3i[node * 8192 + imgh(n, k, k >> 4, 8)] = __float2half_rn(v);
    }
}

// ------------------------------ main kernel --------------------------------

__global__ __launch_bounds__(256, 2)
void mp11_kernel(Params p) {
    extern __shared__ char smem[];
    const int tid = threadIdx.x;
    const int w = tid >> 5, lane = tid & 31;
    const int node = blockIdx.x;
    const int gi = c_gi[node], ki = c_ki[node], nnb = c_n[node];

    const int NY = gridDim.y;
    const int NF = p.nc;
    const int y  = blockIdx.y;
    const int fprev = (int)(((long long)y * NF) / NY);
    const int fnext = (int)(((long long)(y + 1) * NF) / NY);

    if (fnext == fprev) {
        // ==================== TENSOR PATH (R6 body) ====================
        const int m0 = (y - fprev) * 128;
        const int g = lane >> 2, t4 = lane & 3;
        const int wm = w & 3, wn = w >> 2;
        const int sg = (g >> 2) & 1;
        const int awl  = (((t4 >> 1) ^ sg) << 4) + ((t4 & 1) << 3);
        const int aoff = g * 32 + awl;
        const uint32_t sbWB = smem_u32(smem + SM_WB);

        float acc[2][8][4];
        #pragma unroll
        for (int mi = 0; mi < 2; ++mi)
            #pragma unroll
            for (int ni = 0; ni < 8; ++ni)
                #pragma unroll
                for (int r = 0; r < 4; ++r) acc[mi][ni][r] = 0.f;

        const __half* w1i = g_w1i + c_w1i_off[node];
        #pragma unroll 1
        for (int c = 0; c < nnb; ++c) {
            if (c) __syncthreads();
            {
                const __half* ws = w1i + c * 8192;
                #pragma unroll
                for (int i = 0; i < 4; ++i) {
                    int idx = tid + i * 256;
                    CP16(sbWB + idx * 16, ws + idx * 8);
                }
            }
            {
                const int jo = c_nb[node][c] * 64;
                const float* xb = p.x + (size_t)m0 * 1344 + jo;
                #pragma unroll
                for (int i = 0; i < 2; ++i) {
                    int v = tid + i * 256;
                    int m = v >> 2, kt = v & 3;
                    const float* s = xb + (size_t)m * 1344 + kt * 16;
                    float4 A0 = *(const float4*)s;
                    float4 A1 = *(const float4*)(s + 4);
                    float4 A2 = *(const float4*)(s + 8);
                    float4 A3 = *(const float4*)(s + 12);
                    uint4 q0 = make_uint4(pkh2(A0.x, A0.y), pkh2(A2.x, A2.y),
                                          pkh2(A0.z, A0.w), pkh2(A2.z, A2.w));
                    uint4 q1 = make_uint4(pkh2(A1.x, A1.y), pkh2(A3.x, A3.y),
                                          pkh2(A1.z, A1.w), pkh2(A3.z, A3.w));
                    int r = m & 15, R = m >> 4;
                    char* dst = smem + SM_XA + (R * 4 + kt) * 528 + r * 32;
                    int sw = (r & 4) << 2;
                    *(uint4*)(dst + sw) = q0;
                    *(uint4*)(dst + (16 ^ sw)) = q1;
                }
            }
            CP_WAIT();
            __syncthreads();
            #pragma unroll
            for (int k16 = 0; k16 < 4; ++k16) {
                uint2 a[2][2];
                #pragma unroll
                for (int mi = 0; mi < 2; ++mi) {
                    const char* ap = smem + SM_XA + ((wm * 2 + mi) * 4 + k16) * 528 + aoff;
                    a[mi][0] = *(const uint2*)ap;
                    a[mi][1] = *(const uint2*)(ap + 256);
                }
                #pragma unroll
                for (int ni = 0; ni < 8; ++ni) {
                    const char* bp = smem + SM_WB + ((wn * 8 + ni) * 4 + k16) * 256 + aoff;
                    uint2 b = *(const uint2*)bp;
                    domma(acc[0][ni], a[0][0], a[0][1], b);
                    domma(acc[1][ni], a[1][0], a[1][1], b);
                }
            }
        }

        {   // epilogue 1
            const float* bp = p.b1[gi] + ki * 128;
            #pragma unroll
            for (int ni = 0; ni < 8; ++ni) {
                int col0 = wn * 64 + ni * 8 + 2 * t4;
                float2 bb = *(const float2*)(bp + col0);
                int kt = wn * 4 + (ni >> 1);
                int off = awl + ((ni & 1) << 2);
                #pragma unroll
                for (int mi = 0; mi < 2; ++mi) {
                    char* base = smem + SM_HA + ((wm * 2 + mi) * 8 + kt) * 512 + g * 32 + off;
                    *(uint32_t*)base = pkh2(fmaxf(acc[mi][ni][0] + bb.x, 0.f),
                                            fmaxf(acc[mi][ni][1] + bb.y, 0.f));
                    *(uint32_t*)(base + 256) = pkh2(fmaxf(acc[mi][ni][2] + bb.x, 0.f),
                                                    fmaxf(acc[mi][ni][3] + bb.y, 0.f));
                    acc[mi][ni][0] = acc[mi][ni][1] = acc[mi][ni][2] = acc[mi][ni][3] = 0.f;
                }
            }
        }
        __syncthreads();

        const __half* w2i = g_w2i + node * 16384;
        #pragma unroll 1
        for (int c = 0; c < 2; ++c) {
            if (c) __syncthreads();
            {
                const __half* ws = w2i + c * 8192;
                #pragma unroll
                for (int i = 0; i < 4; ++i) {
                    int idx = tid + i * 256;
                    CP16(sbWB + idx * 16, ws + idx * 8);
                }
            }
            CP_WAIT();
            __syncthreads();
            #pragma unroll
            for (int k16 = 0; k16 < 4; ++k16) {
                uint2 a[2][2];
                #pragma unroll
                for (int mi = 0; mi < 2; ++mi) {
                    const char* ap = smem + SM_HA +
                        ((wm * 2 + mi) * 8 + c * 4 + k16) * 512 + aoff;
                    a[mi][0] = *(const uint2*)ap;
                    a[mi][1] = *(const uint2*)(ap + 256);
                }
                #pragma unroll
                for (int ni = 0; ni < 8; ++ni) {
                    const char* bp = smem + SM_WB + ((wn * 8 + ni) * 4 + k16) * 256 + aoff;
                    uint2 b = *(const uint2*)bp;
                    domma(acc[0][ni], a[0][0], a[0][1], b);
                    domma(acc[1][ni], a[1][0], a[1][1], b);
                }
            }
        }
        __syncthreads();

        {   // epilogue 2
            const float* bp = p.b2[gi] + ki * 128;
            #pragma unroll
            for (int ni = 0; ni < 8; ++ni) {
                int col0 = wn * 64 + ni * 8 + 2 * t4;
                float2 bb = *(const float2*)(bp + col0);
                int kt = wn * 4 + (ni >> 1);
                int off = awl + ((ni & 1) << 2);
                #pragma unroll
                for (int mi = 0; mi < 2; ++mi) {
                    char* base = smem + SM_HA + ((wm * 2 + mi) * 8 + kt) * 512 + g * 32 + off;
                    *(uint32_t*)base = pkh2(fmaxf(acc[mi][ni][0] + bb.x, 0.f),
                                            fmaxf(acc[mi][ni][1] + bb.y, 0.f));
                    *(uint32_t*)(base + 256) = pkh2(fmaxf(acc[mi][ni][2] + bb.x, 0.f),
                                                    fmaxf(acc[mi][ni][3] + bb.y, 0.f));
                    acc[mi][ni][0] = acc[mi][ni][1] = acc[mi][ni][2] = acc[mi][ni][3] = 0.f;
                }
            }
        }
        __syncthreads();

        {   // layer 3 W load
            const __half* ws = g_w3i + node * 8192;
            #pragma unroll
            for (int i = 0; i < 4; ++i) {
                int idx = tid + i * 256;
                CP16(sbWB + idx * 16, ws + idx * 8);
            }
        }
        CP_WAIT();
        __syncthreads();

        #pragma unroll
        for (int k16 = 0; k16 < 8; ++k16) {
            uint2 a[2][2];
            #pragma unroll
            for (int mi = 0; mi < 2; ++mi) {
                const char* ap = smem + SM_HA + ((wm * 2 + mi) * 8 + k16) * 512 + aoff;
                a[mi][0] = *(const uint2*)ap;
                a[mi][1] = *(const uint2*)(ap + 256);
            }
            #pragma unroll
            for (int ni = 0; ni < 4; ++ni) {
                const char* bp = smem + SM_WB + ((wn * 4 + ni) * 8 + k16) * 256 + aoff;
                uint2 b = *(const uint2*)bp;
                domma(acc[0][ni], a[0][0], a[0][1], b);
                domma(acc[1][ni], a[1][0], a[1][1], b);
            }
        }

        {   // epilogue 3
            const float* bp = p.b3[gi] + ki * 64;
            const int oj = c_out[node] * 64;
            #pragma unroll
            for (int ni = 0; ni < 4; ++ni) {
                int col0 = wn * 32 + ni * 8 + 2 * t4;
                float2 bb = *(const float2*)(bp + col0);
                #pragma unroll
                for (int mi = 0; mi < 2; ++mi) {
                    size_t ro = (size_t)(m0 + wm * 32 + mi * 16 + g) * 1344 + oj + col0;
                    *(float2*)(p.out + ro) =
                        make_float2(acc[mi][ni][0] + bb.x, acc[mi][ni][1] + bb.y);
                    *(float2*)(p.out + ro + (size_t)8 * 1344) =
                        make_float2(acc[mi][ni][2] + bb.x, acc[mi][ni][3] + bb.y);
                }
            }
        }
    } else {
        // ========== FFMA PATH: 32 rows/CTA, row = lane, cols per warp ======
        const int m0 = p.nt * 128 + fprev * 32;
        const int row = lane;
        float* Xs  = (float*)(smem + SM_FX);     // [32][68]
        float* Hs  = (float*)(smem + SM_FH);     // [32][132]
        float* WsB = (float*)(smem + SM_FW);     // 2 x 4096 floats
        const uint32_t sbW = smem_u32(WsB);

        u64 acc[8];
        #pragma unroll
        for (int n = 0; n < 8; ++n) acc[n] = 0ull;

        const int K1 = nnb * 64;
        const float* w1b = p.w1[gi] + (size_t)ki * K1 * 128;
        const float* w2b = p.w2[gi] + (size_t)ki * 16384;
        const float* w3b = p.w3[gi] + (size_t)ki * 8192;

        // prologue: W1 chunk0 -> buf0
        #pragma unroll
        for (int i = 0; i < 4; ++i) {
            int idx = tid + i * 256;
            CP16(sbW + idx * 16, w1b + idx * 4);
        }
        CP_COMMIT();

        int gc = 0;
        // ------------------- Layer 1 -------------------
        #pragma unroll 1
        for (int c = 0; c < nnb; ++c) {
            __syncthreads();
            {   // stage X joint c: 32 rows x 64 cols -> Xs[32][68]
                const float* xb = p.x + (size_t)m0 * 1344 + c_nb[node][c] * 64;
                #pragma unroll
                for (int i = 0; i < 2; ++i) {
                    int v = tid + i * 256;
                    int r = v >> 4, q = v & 15;
                    *(float4*)(Xs + r * 68 + q * 4) =
                        *(const float4*)(xb + (size_t)r * 1344 + q * 4);
                }
            }
            #pragma unroll 1
            for (int h = 0; h < 2; ++h) {
                if (h) __syncthreads();
                {   // issue next W chunk (or W2 chunk0)
                    const float* nsrc = (gc + 1 < 2 * nnb)
                        ? (w1b + (size_t)(gc + 1) * 4096) : w2b;
                    uint32_t nd = sbW + ((gc + 1) & 1) * 16384;
                    #pragma unroll
                    for (int i = 0; i < 4; ++i) {
                        int idx = tid + i * 256;
                        CP16(nd + idx * 16, nsrc + idx * 4);
                    }
                    CP_COMMIT();
                }
                CP_WAITG1();
                __syncthreads();
                const float* wsb = WsB + (gc & 1) * 4096;
                #pragma unroll 2
                for (int q = 0; q < 8; ++q) {
                    float4 xq = *(const float4*)(Xs + row * 68 + h * 32 + q * 4);
                    #pragma unroll
                    for (int k4 = 0; k4 < 4; ++k4) {
                        const ulonglong2* wr =
                            (const ulonglong2*)(wsb + (q * 4 + k4) * 128 + w * 16);
                        ulonglong2 p0 = wr[0], p1 = wr[1], p2 = wr[2], p3 = wr[3];
                        u64 xv = dup2(k4 == 0 ? xq.x : k4 == 1 ? xq.y : k4 == 2 ? xq.z : xq.w);
                        FFMA2(acc[0], xv, p0.x); FFMA2(acc[1], xv, p0.y);
                        FFMA2(acc[2], xv, p1.x); FFMA2(acc[3], xv, p1.y);
                        FFMA2(acc[4], xv, p2.x); FFMA2(acc[5], xv, p2.y);
                        FFMA2(acc[6], xv, p3.x); FFMA2(acc[7], xv, p3.y);
                    }
                }
                ++gc;
            }
        }
        __syncthreads();

        // epilogue 1 -> Hs
        {
            const float* bp = p.b1[gi] + ki * 128 + w * 16;
            float* hr = Hs + row * 132 + w * 16;
            #pragma unroll
            for (int t = 0; t < 4; ++t) {
                float l0, h0, l1, h1;
                upk(acc[2 * t], l0, h0);
                upk(acc[2 * t + 1], l1, h1);
                float4 v = make_float4(fmaxf(l0 + bp[4 * t], 0.f),
                                       fmaxf(h0 + bp[4 * t + 1], 0.f),
                                       fmaxf(l1 + bp[4 * t + 2], 0.f),
                                       fmaxf(h1 + bp[4 * t + 3], 0.f));
                *(float4*)(hr + 4 * t) = v;
                acc[2 * t] = 0ull; acc[2 * t + 1] = 0ull;
            }
        }
        __syncthreads();

        // ------------------- Layer 2 -------------------
        #pragma unroll 1
        for (int c2 = 0; c2 < 4; ++c2) {
            if (c2) __syncthreads();
            {
                const float* nsrc = (c2 < 3) ? (w2b + (size_t)(c2 + 1) * 4096) : w3b;
                uint32_t nd = sbW + ((gc + 1) & 1) * 16384;
                const int nq = (c2 < 3) ? 4 : 2;
                for (int i = 0; i < nq; ++i) {
                    int idx = tid + i * 256;
                    CP16(nd + idx * 16, nsrc + idx * 4);
                }
                CP_COMMIT();
            }
            CP_WAITG1();
            __syncthreads();
            const float* wsb = WsB + (gc & 1) * 4096;
            #pragma unroll 2
            for (int q = 0; q < 8; ++q) {
                float4 xq = *(const float4*)(Hs + row * 132 + c2 * 32 + q * 4);
                #pragma unroll
                for (int k4 = 0; k4 < 4; ++k4) {
                    const ulonglong2* wr =
                        (const ulonglong2*)(wsb + (q * 4 + k4) * 128 + w * 16);
                    ulonglong2 p0 = wr[0], p1 = wr[1], p2 = wr[2], p3 = wr[3];
                    u64 xv = dup2(k4 == 0 ? xq.x : k4 == 1 ? xq.y : k4 == 2 ? xq.z : xq.w);
                    FFMA2(acc[0], xv, p0.x); FFMA2(acc[1], xv, p0.y);
                    FFMA2(acc[2], xv, p1.x); FFMA2(acc[3], xv, p1.y);
                    FFMA2(acc[4], xv, p2.x); FFMA2(acc[5], xv, p2.y);
                    FFMA2(acc[6], xv, p3.x); FFMA2(acc[7], xv, p3.y);
                }
            }
            ++gc;
        }
        __syncthreads();

        // epilogue 2 -> Hs (in place)
        {
            const float* bp = p.b2[gi] + ki * 128 + w * 16;
            float* hr = Hs + row * 132 + w * 16;
            #pragma unroll
            for (int t = 0; t < 4; ++t) {
                float l0, h0, l1, h1;
                upk(acc[2 * t], l0, h0);
                upk(acc[2 * t + 1], l1, h1);
                float4 v = make_float4(fmaxf(l0 + bp[4 * t], 0.f),
                                       fmaxf(h0 + bp[4 * t + 1], 0.f),
                                       fmaxf(l1 + bp[4 * t + 2], 0.f),
                                       fmaxf(h1 + bp[4 * t + 3], 0.f));
                *(float4*)(hr + 4 * t) = v;
                acc[2 * t] = 0ull; acc[2 * t + 1] = 0ull;
            }
        }
        __syncthreads();

        // ------------------- Layer 3 (cols [8w, 8w+8)) -------------------
        #pragma unroll 1
        for (int c3 = 0; c3 < 4; ++c3) {
            if (c3) __syncthreads();
            if (c3 < 3) {
                const float* nsrc = w3b + (size_t)(c3 + 1) * 2048;
                uint32_t nd = sbW + ((gc + 1) & 1) * 16384;
                for (int i = 0; i < 2; ++i) {
                    int idx = tid + i * 256;
                    CP16(nd + idx * 16, nsrc + idx * 4);
                }
                CP_COMMIT();
                CP_WAITG1();
            } else {
                CP_WAIT0();
            }
            __syncthreads();
            const float* wsb = WsB + (gc & 1) * 4096;
            #pragma unroll 2
            for (int q = 0; q < 8; ++q) {
                float4 xq = *(const float4*)(Hs + row * 132 + c3 * 32 + q * 4);
                #pragma unroll
                for (int k4 = 0; k4 < 4; ++k4) {
                    const ulonglong2* wr =
                        (const ulonglong2*)(wsb + (q * 4 + k4) * 64 + w * 8);
                    ulonglong2 p0 = wr[0], p1 = wr[1];
                    u64 xv = dup2(k4 == 0 ? xq.x : k4 == 1 ? xq.y : k4 == 2 ? xq.z : xq.w);
                    FFMA2(acc[0], xv, p0.x); FFMA2(acc[1], xv, p0.y);
                    FFMA2(acc[2], xv, p1.x); FFMA2(acc[3], xv, p1.y);
                }
            }
            ++gc;
        }

        // epilogue 3 -> gmem
        {
            const float* bp = p.b3[gi] + ki * 64 + w * 8;
            const int oj = c_out[node] * 64;
            float* orow = p.out + (size_t)(m0 + row) * 1344 + oj + w * 8;
            #pragma unroll
            for (int t = 0; t < 2; ++t) {
                float l0, h0, l1, h1;
                upk(acc[2 * t], l0, h0);
                upk(acc[2 * t + 1], l1, h1);
                float4 v = make_float4(l0 + bp[4 * t], h0 + bp[4 * t + 1],
                                       l1 + bp[4 * t + 2], h1 + bp[4 * t + 3]);
                *(float4*)(orow + 4 * t) = v;
            }
        }
    }
}

// ------------------------------ launch -------------------------------------

extern "C" void kernel_launch(void* const* d_in, const int* in_sizes, int n_in,
                              void* d_out, int out_size) {
    (void)n_in; (void)out_size;
    Params p;
    p.x = (const float*)d_in[0];
    int idx = 1;
    for (int gi = 0; gi < 5; ++gi) {
        p.w1[gi] = (const float*)d_in[idx++];
        p.b1[gi] = (const float*)d_in[idx++];
        p.w2[gi] = (const float*)d_in[idx++];
        p.b2[gi] = (const float*)d_in[idx++];
        p.w3[gi] = (const float*)d_in[idx++];
        p.b3[gi] = (const float*)d_in[idx++];
    }
    p.out = (float*)d_out;

    const int B  = in_sizes[0] / (21 * 64);
    const int YT = B / 128;                 // total 128-row tiles
    p.nt = (YT * 113) / 128;                // tensor tiles (452 for YT=512)
    p.nc = (YT - p.nt) * 4;                 // ffma 32-row CTAs (240)

    prep_kernel<<<dim3(192, 21, 3), 256>>>(p);

    cudaFuncSetAttribute(mp11_kernel, cudaFuncAttributeMaxDynamicSharedMemorySize,
                         SMEM_TOTAL);
    dim3 grid(21, p.nt + p.nc);
    mp11_kernel<<<grid, 256, SMEM_TOTAL>>>(p);
}

// round 12
// speedup vs baseline: 1.9498x; 1.9498x over previous
#include <cuda_runtime.h>
#include <cuda_fp16.h>
#include <cstdint>

// ---------------------------------------------------------------------------
// Round 12: R7 tensor kernel + software-pipelined fragment loads.
// Theory: tensor pipe only 37.5% busy at the "0.2 instr/cyc" plateau ->
// not a dispatch cap but exposed LDS->MMA latency (1 warp/SMSP in R7).
// Fix: group all B-frag LDS per k16 step; register-double-buffer A-frags.
// Hybrid FFMA experiments (R8-R11) falsified and removed.
// ---------------------------------------------------------------------------

struct Params {
    const float* x;
    const float* w1[5]; const float* b1[5];
    const float* w2[5]; const float* b2[5];
    const float* w3[5]; const float* b3[5];
    float* out;
};

__constant__ int c_gi[21]  = {0,1,1,1,2,2,3,3,3,3,3,3,3,3,3,3,4,4,4,4,4};
__constant__ int c_ki[21]  = {0,0,1,2,0,1,0,1,2,3,4,5,6,7,8,9,0,1,2,3,4};
__constant__ int c_n[21]   = {6,5,5,5,4,4,3,3,3,3,3,3,3,3,3,3,2,2,2,2,2};
__constant__ int c_out[21] = {0,5,9,13,1,17,2,3,6,7,10,11,14,15,18,19,4,8,12,16,20};
__constant__ int c_nb[21][6] = {
    {0,1,5,9,13,17},
    {0,5,6,1,9,0},  {0,9,10,5,13,0}, {0,13,14,9,17,0},
    {0,1,2,5,0,0},  {0,17,18,13,0,0},
    {1,2,3,0,0,0},  {2,3,4,0,0,0},
    {5,6,7,0,0,0},  {6,7,8,0,0,0},
    {9,10,11,0,0,0},{10,11,12,0,0,0},
    {13,14,15,0,0,0},{14,15,16,0,0,0},
    {17,18,19,0,0,0},{18,19,20,0,0,0},
    {3,4,0,0,0,0},  {7,8,0,0,0,0}, {11,12,0,0,0,0},
    {15,16,0,0,0,0},{19,20,0,0,0,0}
};
// per-node half-offset of W1 image (chunks of 8192 halves = one 64-k slab)
__constant__ int c_w1i_off[21] = {
    0,49152,90112,131072,172032,204800,
    237568,262144,286720,311296,335872,360448,385024,409600,434176,458752,
    483328,499712,516096,532480,548864
};

// Pre-shuffled fp16 weight images (exact SMEM byte layout)
__device__ __align__(16) __half g_w1i[565248];
__device__ __align__(16) __half g_w2i[344064];   // 21 * 2 * 8192
__device__ __align__(16) __half g_w3i[172032];   // 21 * 8192

// SMEM map (bytes). Tiles: 16 rows x 32B. HA 512B, XA 528B (pad), WB 256B.
#define SM_HA 0                      // 64 tiles * 512 = 32768
#define SM_XA 32768                  // 2 bufs * 32 tiles * 528 = 33792
#define XA_BUF 16896
#define SM_WB 66560                  // 2 bufs * 16384
#define WB_BUF 16384
#define SMEM_TOTAL 99328

__device__ __forceinline__ uint32_t pkh2(float lo, float hi) {
    uint32_t r;   // low half = lo
    asm("cvt.rn.f16x2.f32 %0, %1, %2;" : "=r"(r) : "f"(hi), "f"(lo));
    return r;
}

__device__ __forceinline__ void mma16(float c[4],
                                      uint32_t a0, uint32_t a1, uint32_t a2, uint32_t a3,
                                      uint32_t b0, uint32_t b1) {
    asm volatile(
        "mma.sync.aligned.m16n8k16.row.col.f32.f16.f16.f32 "
        "{%0,%1,%2,%3},{%4,%5,%6,%7},{%8,%9},{%0,%1,%2,%3};"
        : "+f"(c[0]), "+f"(c[1]), "+f"(c[2]), "+f"(c[3])
        : "r"(a0), "r"(a1), "r"(a2), "r"(a3), "r"(b0), "r"(b1));
}
__device__ __forceinline__ void domma(float c[4], uint2 Pg, uint2 Pg8, uint2 Pb) {
    mma16(c, Pg.x, Pg8.x, Pg.y, Pg8.y, Pb.x, Pb.y);
}

#define CP16(dst, src) \
    asm volatile("cp.async.ca.shared.global [%0], [%1], 16;" :: "r"(dst), "l"(src))
#define CP_COMMIT() asm volatile("cp.async.commit_group;" ::: "memory")
#define CP_WAIT0()  asm volatile("cp.async.wait_group 0;" ::: "memory")

__device__ __forceinline__ uint32_t smem_u32(const void* p) {
    uint32_t a;
    asm("{ .reg .u64 t; cvta.to.shared.u64 t, %1; cvt.u32.u64 %0, t; }"
        : "=r"(a) : "l"(p));
    return a;
}

// ------------------------------ prep kernel --------------------------------
// Identical to R6/R7 (verified): B tile stride = 128 halves.
__device__ __forceinline__ int imgh(int n, int k, int K16, int NK16c) {
    int jw = (k & 15) >> 1, lo = k & 1;
    int rn = n & 7, NB = n >> 3, s = (rn >> 2) & 1;
    return (NB * NK16c + K16) * 128 + rn * 16 +
           ((((jw >> 1) & 1) ^ s) << 3) + ((jw & 1) << 2) + ((jw >> 2) << 1) + lo;
}

__global__ void prep_kernel(Params p) {
    const int node = blockIdx.y;
    const int gi = c_gi[node], ki = c_ki[node], nnb = c_n[node];
    const int i = blockIdx.x * 256 + threadIdx.x;
    if (blockIdx.z == 0) {
        const int K1 = nnb * 64;
        if (i >= 128 * K1) return;
        const int k = i >> 7, n = i & 127;
        float v = p.w1[gi][((size_t)ki * K1 + k) * 128 + n];
        g_w1i[c_w1i_off[node] + (k >> 6) * 8192 + imgh(n, k, (k >> 4) & 3, 4)] =
            __float2half_rn(v);
    } else if (blockIdx.z == 1) {
        if (i >= 16384) return;
        const int k = i >> 7, n = i & 127;
        float v = p.w2[gi][(size_t)ki * 16384 + (size_t)k * 128 + n];
        g_w2i[node * 16384 + (k >> 6) * 8192 + imgh(n, k, (k >> 4) & 3, 4)] =
            __float2half_rn(v);
    } else {
        if (i >= 8192) return;
        const int k = i >> 6, n = i & 63;
        float v = p.w3[gi][(size_t)ki * 8192 + (size_t)k * 64 + n];
        g_w3i[node * 8192 + imgh(n, k, k >> 4, 8)] = __float2half_rn(v);
    }
}

// ------------------------------ main kernel --------------------------------

__global__ __launch_bounds__(128, 2)
void mp12_kernel(Params p) {
    extern __shared__ char smem[];
    const int tid = threadIdx.x;
    const int w = tid >> 5, lane = tid & 31;
    const int g = lane >> 2, t4 = lane & 3;
    const int node = blockIdx.x;
    const int m0 = blockIdx.y * 128;
    const int gi = c_gi[node], ki = c_ki[node], nnb = c_n[node];
    const int wm = w & 1, wn = w >> 1;          // 2M x 2N grid of 64x64 tiles
    const int sg = (g >> 2) & 1;
    const int awl  = (((t4 >> 1) ^ sg) << 4) + ((t4 & 1) << 3);
    const int aoff = g * 32 + awl;

    const uint32_t sbWB = smem_u32(smem + SM_WB);

    float acc[4][8][4];
    #pragma unroll
    for (int mi = 0; mi < 4; ++mi)
        #pragma unroll
        for (int ni = 0; ni < 8; ++ni)
            #pragma unroll
            for (int r = 0; r < 4; ++r) acc[mi][ni][r] = 0.f;

    #define ISSUE_W(ws, buf) do {                                         \
        uint32_t _d = sbWB + (buf) * WB_BUF;                              \
        const __half* _s = (ws);                                          \
        _Pragma("unroll")                                                 \
        for (int _i = 0; _i < 8; ++_i) {                                  \
            int _idx = tid + _i * 128;                                    \
            CP16(_d + _idx * 16, _s + _idx * 8);                          \
        }                                                                 \
        CP_COMMIT();                                                      \
    } while (0)

    #define STORE_X(joint, buf) do {                                      \
        const float* _xb = p.x + (size_t)m0 * 1344 + (joint) * 64;        \
        char* _xa = smem + SM_XA + (buf) * XA_BUF;                        \
        _Pragma("unroll")                                                 \
        for (int _i = 0; _i < 4; ++_i) {                                  \
            int _v = tid + _i * 128;                                      \
            int _m = _v >> 2, _kt = _v & 3;                               \
            const float* _s = _xb + (size_t)_m * 1344 + _kt * 16;         \
            float4 A0 = *(const float4*)_s;                               \
            float4 A1 = *(const float4*)(_s + 4);                         \
            float4 A2 = *(const float4*)(_s + 8);                         \
            float4 A3 = *(const float4*)(_s + 12);                        \
            uint4 q0 = make_uint4(pkh2(A0.x, A0.y), pkh2(A2.x, A2.y),     \
                                  pkh2(A0.z, A0.w), pkh2(A2.z, A2.w));    \
            uint4 q1 = make_uint4(pkh2(A1.x, A1.y), pkh2(A3.x, A3.y),     \
                                  pkh2(A1.z, A1.w), pkh2(A3.z, A3.w));    \
            int _r = _m & 15, _R = _m >> 4;                               \
            char* _dst = _xa + (_R * 4 + _kt) * 528 + _r * 32;            \
            int _sw = (_r & 4) << 2;                                      \
            *(uint4*)(_dst + _sw) = q0;                                   \
            *(uint4*)(_dst + (16 ^ _sw)) = q1;                            \
        }                                                                 \
    } while (0)

    // Load A-fragment pair for (base, k16) from a tile region with stride.
    #define LOAD_A(dst, base, tile_idx, stride) do {                      \
        _Pragma("unroll")                                                 \
        for (int _mi = 0; _mi < 4; ++_mi) {                               \
            const char* _ap = (base) + ((tile_idx) + _mi * (stride)) * 0 +\
                0; (void)_ap;                                             \
        }                                                                 \
    } while (0)

    const __half* w1i = g_w1i + c_w1i_off[node];
    const __half* w2i = g_w2i + node * 16384;
    const __half* w3i = g_w3i + node * 8192;

    // prologue: chunk 0 into buffers 0
    ISSUE_W(w1i, 0);
    STORE_X(c_nb[node][0], 0);
    CP_WAIT0();
    __syncthreads();

    // ============================ Layer 1 ================================
    #pragma unroll 1
    for (int c = 0; c < nnb; ++c) {
        const int cu = c & 1, nx = cu ^ 1;
        if (c + 1 < nnb) {
            ISSUE_W(w1i + (c + 1) * 8192, nx);
            STORE_X(c_nb[node][c + 1], nx);
        } else {
            ISSUE_W(w2i, nx);
        }
        const char* xa = smem + SM_XA + cu * XA_BUF;
        const char* wb = smem + SM_WB + cu * WB_BUF;

        // pipelined fragment loads: A double-buffered, B grouped per step
        uint2 a[2][4][2];
        #pragma unroll
        for (int mi = 0; mi < 4; ++mi) {
            const char* ap = xa + ((wm * 4 + mi) * 4 + 0) * 528 + aoff;
            a[0][mi][0] = *(const uint2*)ap;
            a[0][mi][1] = *(const uint2*)(ap + 256);
        }
        #pragma unroll
        for (int k16 = 0; k16 < 4; ++k16) {
            const int cb = k16 & 1, nb = cb ^ 1;
            uint2 b[8];
            #pragma unroll
            for (int ni = 0; ni < 8; ++ni)
                b[ni] = *(const uint2*)(wb + ((wn * 8 + ni) * 4 + k16) * 256 + aoff);
            if (k16 < 3) {
                #pragma unroll
                for (int mi = 0; mi < 4; ++mi) {
                    const char* ap = xa + ((wm * 4 + mi) * 4 + k16 + 1) * 528 + aoff;
                    a[nb][mi][0] = *(const uint2*)ap;
                    a[nb][mi][1] = *(const uint2*)(ap + 256);
                }
            }
            #pragma unroll
            for (int ni = 0; ni < 8; ++ni)
                #pragma unroll
                for (int mi = 0; mi < 4; ++mi)
                    domma(acc[mi][ni], a[cb][mi][0], a[cb][mi][1], b[ni]);
        }
        CP_WAIT0();
        __syncthreads();
    }
    const int b0 = nnb & 1;   // W2 chunk0 buffer

    // epilogue 1: prefetch W2 chunk1, bias + relu -> HA
    ISSUE_W(w2i + 8192, b0 ^ 1);
    {
        const float* bp = p.b1[gi] + ki * 128;
        #pragma unroll
        for (int ni = 0; ni < 8; ++ni) {
            int col0 = wn * 64 + ni * 8 + 2 * t4;
            float2 bb = *(const float2*)(bp + col0);
            int kt = wn * 4 + (ni >> 1);
            int off = awl + ((ni & 1) << 2);
            #pragma unroll
            for (int mi = 0; mi < 4; ++mi) {
                char* base = smem + SM_HA + ((wm * 4 + mi) * 8 + kt) * 512 + g * 32 + off;
                *(uint32_t*)base = pkh2(fmaxf(acc[mi][ni][0] + bb.x, 0.f),
                                        fmaxf(acc[mi][ni][1] + bb.y, 0.f));
                *(uint32_t*)(base + 256) = pkh2(fmaxf(acc[mi][ni][2] + bb.x, 0.f),
                                                fmaxf(acc[mi][ni][3] + bb.y, 0.f));
                acc[mi][ni][0] = acc[mi][ni][1] = acc[mi][ni][2] = acc[mi][ni][3] = 0.f;
            }
        }
    }
    __syncthreads();

    // ============================ Layer 2 ================================
    #pragma unroll 1
    for (int c = 0; c < 2; ++c) {
        if (c == 1) ISSUE_W(w3i, b0);   // prefetch W3 into chunk0's buffer
        const char* wb = smem + SM_WB + ((c == 0) ? b0 : (b0 ^ 1)) * WB_BUF;

        uint2 a[2][4][2];
        #pragma unroll
        for (int mi = 0; mi < 4; ++mi) {
            const char* ap = smem + SM_HA + ((wm * 4 + mi) * 8 + c * 4) * 512 + aoff;
            a[0][mi][0] = *(const uint2*)ap;
            a[0][mi][1] = *(const uint2*)(ap + 256);
        }
        #pragma unroll
        for (int k16 = 0; k16 < 4; ++k16) {
            const int cb = k16 & 1, nb = cb ^ 1;
            uint2 b[8];
            #pragma unroll
            for (int ni = 0; ni < 8; ++ni)
                b[ni] = *(const uint2*)(wb + ((wn * 8 + ni) * 4 + k16) * 256 + aoff);
            if (k16 < 3) {
                #pragma unroll
                for (int mi = 0; mi < 4; ++mi) {
                    const char* ap = smem + SM_HA +
                        ((wm * 4 + mi) * 8 + c * 4 + k16 + 1) * 512 + aoff;
                    a[nb][mi][0] = *(const uint2*)ap;
                    a[nb][mi][1] = *(const uint2*)(ap + 256);
                }
            }
            #pragma unroll
            for (int ni = 0; ni < 8; ++ni)
                #pragma unroll
                for (int mi = 0; mi < 4; ++mi)
                    domma(acc[mi][ni], a[cb][mi][0], a[cb][mi][1], b[ni]);
        }
        CP_WAIT0();
        __syncthreads();
    }

    // epilogue 2: bias + relu -> HA (in place; layer-2 reads done at barrier)
    {
        const float* bp = p.b2[gi] + ki * 128;
        #pragma unroll
        for (int ni = 0; ni < 8; ++ni) {
            int col0 = wn * 64 + ni * 8 + 2 * t4;
            float2 bb = *(const float2*)(bp + col0);
            int kt = wn * 4 + (ni >> 1);
            int off = awl + ((ni & 1) << 2);
            #pragma unroll
            for (int mi = 0; mi < 4; ++mi) {
                char* base = smem + SM_HA + ((wm * 4 + mi) * 8 + kt) * 512 + g * 32 + off;
                *(uint32_t*)base = pkh2(fmaxf(acc[mi][ni][0] + bb.x, 0.f),
                                        fmaxf(acc[mi][ni][1] + bb.y, 0.f));
                *(uint32_t*)(base + 256) = pkh2(fmaxf(acc[mi][ni][2] + bb.x, 0.f),
                                                fmaxf(acc[mi][ni][3] + bb.y, 0.f));
                acc[mi][ni][0] = acc[mi][ni][1] = acc[mi][ni][2] = acc[mi][ni][3] = 0.f;
            }
        }
    }
    __syncthreads();

    // ============================ Layer 3 ================================
    {
        const char* wb = smem + SM_WB + b0 * WB_BUF;   // W3 (waited at L2 end)
        uint2 a[2][4][2];
        #pragma unroll
        for (int mi = 0; mi < 4; ++mi) {
            const char* ap = smem + SM_HA + ((wm * 4 + mi) * 8 + 0) * 512 + aoff;
            a[0][mi][0] = *(const uint2*)ap;
            a[0][mi][1] = *(const uint2*)(ap + 256);
        }
        #pragma unroll
        for (int k16 = 0; k16 < 8; ++k16) {
            const int cb = k16 & 1, nb = cb ^ 1;
            uint2 b[4];
            #pragma unroll
            for (int ni = 0; ni < 4; ++ni)
                b[ni] = *(const uint2*)(wb + ((wn * 4 + ni) * 8 + k16) * 256 + aoff);
            if (k16 < 7) {
                #pragma unroll
                for (int mi = 0; mi < 4; ++mi) {
                    const char* ap = smem + SM_HA +
                        ((wm * 4 + mi) * 8 + k16 + 1) * 512 + aoff;
                    a[nb][mi][0] = *(const uint2*)ap;
                    a[nb][mi][1] = *(const uint2*)(ap + 256);
                }
            }
            #pragma unroll
            for (int ni = 0; ni < 4; ++ni)
                #pragma unroll
                for (int mi = 0; mi < 4; ++mi)
                    domma(acc[mi][ni], a[cb][mi][0], a[cb][mi][1], b[ni]);
        }
    }

    // epilogue 3: bias, f32 STG.64 direct
    {
        const float* bp = p.b3[gi] + ki * 64;
        const int oj = c_out[node] * 64;
        #pragma unroll
        for (int ni = 0; ni < 4; ++ni) {
            int col0 = wn * 32 + ni * 8 + 2 * t4;
            float2 bb = *(const float2*)(bp + col0);
            #pragma unroll
            for (int mi = 0; mi < 4; ++mi) {
                size_t ro = (size_t)(m0 + wm * 64 + mi * 16 + g) * 1344 + oj + col0;
                *(float2*)(p.out + ro) =
                    make_float2(acc[mi][ni][0] + bb.x, acc[mi][ni][1] + bb.y);
                *(float2*)(p.out + ro + (size_t)8 * 1344) =
                    make_float2(acc[mi][ni][2] + bb.x, acc[mi][ni][3] + bb.y);
            }
        }
    }
    #undef ISSUE_W
    #undef STORE_X
    #undef LOAD_A
}

// ------------------------------ launch -------------------------------------

extern "C" void kernel_launch(void* const* d_in, const int* in_sizes, int n_in,
                              void* d_out, int out_size) {
    (void)n_in; (void)out_size;
    Params p;
    p.x = (const float*)d_in[0];
    int idx = 1;
    for (int gi = 0; gi < 5; ++gi) {
        p.w1[gi] = (const float*)d_in[idx++];
        p.b1[gi] = (const float*)d_in[idx++];
        p.w2[gi] = (const float*)d_in[idx++];
        p.b2[gi] = (const float*)d_in[idx++];
        p.w3[gi] = (const float*)d_in[idx++];
        p.b3[gi] = (const float*)d_in[idx++];
    }
    p.out = (float*)d_out;

    const int B = in_sizes[0] / (21 * 64);

    prep_kernel<<<dim3(192, 21, 3), 256>>>(p);

    cudaFuncSetAttribute(mp12_kernel, cudaFuncAttributeMaxDynamicSharedMemorySize,
                         SMEM_TOTAL);
    dim3 grid(21, B / 128);
    mp12_kernel<<<grid, 128, SMEM_TOTAL>>>(p);
}